// round 2
// baseline (speedup 1.0000x reference)
#include <cuda_runtime.h>

#define NN   2048
#define FIN  16
#define TT   12
#define FOUT 32
#define BB   8
#define FT   (FIN*TT)   // 192
#define TM   32
#define KT   32

// scratch: Chebyshev supports and S^2
__device__ float g_S [NN*(size_t)NN];
__device__ float g_S2[NN*(size_t)NN];

// ---------------------------------------------------------------------------
// Kernel 1: S = softmax(relu(E E^T), axis=1)   (one block per row)
// ---------------------------------------------------------------------------
__global__ __launch_bounds__(256)
void k_supports(const float* __restrict__ E) {
    const int i   = blockIdx.x;
    const int tid = threadIdx.x;
    __shared__ float ei[FIN];
    __shared__ float row[NN];
    __shared__ float red[8];
    __shared__ float bcast0, bcast1;

    if (tid < FIN) ei[tid] = E[i*FIN + tid];
    __syncthreads();

    float lmax = 0.0f;  // relu output >= 0
    for (int j = tid; j < NN; j += 256) {
        const float4* ej = reinterpret_cast<const float4*>(E + (size_t)j*FIN);
        float dot = 0.f;
        #pragma unroll
        for (int q = 0; q < 4; q++) {
            float4 v = ej[q];
            dot += v.x*ei[q*4+0] + v.y*ei[q*4+1] + v.z*ei[q*4+2] + v.w*ei[q*4+3];
        }
        float r = fmaxf(dot, 0.f);
        row[j] = r;
        lmax = fmaxf(lmax, r);
    }
    #pragma unroll
    for (int o = 16; o > 0; o >>= 1) lmax = fmaxf(lmax, __shfl_xor_sync(0xffffffffu, lmax, o));
    if ((tid & 31) == 0) red[tid >> 5] = lmax;
    __syncthreads();
    if (tid == 0) {
        float m = red[0];
        #pragma unroll
        for (int w = 1; w < 8; w++) m = fmaxf(m, red[w]);
        bcast0 = m;
    }
    __syncthreads();
    const float bmax = bcast0;

    float lsum = 0.f;
    for (int j = tid; j < NN; j += 256) {
        float e = expf(row[j] - bmax);
        row[j] = e;
        lsum += e;
    }
    #pragma unroll
    for (int o = 16; o > 0; o >>= 1) lsum += __shfl_xor_sync(0xffffffffu, lsum, o);
    if ((tid & 31) == 0) red[tid >> 5] = lsum;
    __syncthreads();
    if (tid == 0) {
        float s = 0.f;
        #pragma unroll
        for (int w = 0; w < 8; w++) s += red[w];
        bcast1 = 1.0f / s;
    }
    __syncthreads();
    const float inv = bcast1;
    for (int j = tid; j < NN; j += 256)
        g_S[(size_t)i*NN + j] = row[j] * inv;
}

// ---------------------------------------------------------------------------
// Kernel 2: S2 = S @ S   (128x128 tile, 8x8 per thread, fp32)
// ---------------------------------------------------------------------------
__global__ __launch_bounds__(256)
void k_gemm_ss() {
    const float* A = g_S;
    const float* B = g_S;
    float* C = g_S2;
    __shared__ float As[8][132];
    __shared__ float Bs[8][128];

    const int tid = threadIdx.x;
    const int tx = tid & 15, ty = tid >> 4;
    const int i0 = blockIdx.y * 128, j0 = blockIdx.x * 128;

    float acc[8][8] = {};

    for (int k0 = 0; k0 < NN; k0 += 8) {
        {   // A tile 128x8, transposed into As
            int row = tid >> 1, q = tid & 1;
            float4 av = *reinterpret_cast<const float4*>(A + (size_t)(i0+row)*NN + k0 + q*4);
            As[q*4+0][row] = av.x; As[q*4+1][row] = av.y;
            As[q*4+2][row] = av.z; As[q*4+3][row] = av.w;
        }
        {   // B tile 8x128
            int row = tid >> 5, c4 = tid & 31;
            float4 bv = *reinterpret_cast<const float4*>(B + (size_t)(k0+row)*NN + j0 + c4*4);
            *reinterpret_cast<float4*>(&Bs[row][c4*4]) = bv;
        }
        __syncthreads();
        #pragma unroll
        for (int k = 0; k < 8; k++) {
            float a[8], bb[8];
            #pragma unroll
            for (int i = 0; i < 8; i++) a[i]  = As[k][ty*8+i];
            #pragma unroll
            for (int j = 0; j < 8; j++) bb[j] = Bs[k][tx*8+j];
            #pragma unroll
            for (int i = 0; i < 8; i++)
                #pragma unroll
                for (int j = 0; j < 8; j++)
                    acc[i][j] = fmaf(a[i], bb[j], acc[i][j]);
        }
        __syncthreads();
    }
    #pragma unroll
    for (int i = 0; i < 8; i++) {
        float* crow = C + (size_t)(i0 + ty*8 + i)*NN + j0 + tx*8;
        #pragma unroll
        for (int j = 0; j < 8; j += 4) {
            float4 v = make_float4(acc[i][j], acc[i][j+1], acc[i][j+2], acc[i][j+3]);
            *reinterpret_cast<float4*>(crow + j) = v;
        }
    }
}

// ---------------------------------------------------------------------------
// Kernel 3: fused masked dual-GEMM + theta epilogue + relu
//   rhs1[m,ft] = sum_n  S[n,m]*A[b,n,m]*x[b,n,ft]
//   rhs2[m,ft] = sum_n 2*S2[n,m]*A[b,n,m]*x[b,n,ft]
//   out[m,o,t] = relu( sum_f rhs1*th1 + rhs2*th2 + A[b,m,m]*x[b,m,f,t]*(th0-th2) )
// ---------------------------------------------------------------------------
__global__ __launch_bounds__(256)
void k_main(const float* __restrict__ x, const float* __restrict__ A,
            const float* __restrict__ theta, float* __restrict__ out) {
    extern __shared__ float sm[];
    float* xs = sm;             // KT*FT = 6144 floats
    float* w1 = sm + 6144;      // KT*TM = 1024
    float* w2 = sm + 7168;      // 1024

    const int b   = blockIdx.y;
    const int m0  = blockIdx.x * TM;
    const int tid = threadIdx.x;
    const int tf  = tid & 31;   // 0..31 (ft lane)
    const int tm  = tid >> 5;   // 0..7  (m group)

    float acc1[4][6] = {};
    float acc2[4][6] = {};

    const float* xb = x + (size_t)b*NN*FT;
    const float* Ab = A + (size_t)b*NN*NN;

    for (int n0 = 0; n0 < NN; n0 += KT) {
        // stage x tile (contiguous KT*FT block)
        const float4* x4  = reinterpret_cast<const float4*>(xb + (size_t)n0*FT);
        float4* xs4 = reinterpret_cast<float4*>(xs);
        #pragma unroll
        for (int i = tid; i < KT*FT/4; i += 256) xs4[i] = x4[i];
        // stage masked weight tiles
        #pragma unroll
        for (int i = tid; i < KT*TM; i += 256) {
            int kk = i >> 5;
            int m  = i & 31;
            size_t off = (size_t)(n0 + kk)*NN + m0 + m;
            float a = Ab[off];
            w1[i] = g_S [off] * a;
            w2[i] = 2.0f * g_S2[off] * a;
        }
        __syncthreads();
        #pragma unroll 4
        for (int kk = 0; kk < KT; kk++) {
            float xv[6];
            #pragma unroll
            for (int c = 0; c < 6; c++) xv[c] = xs[kk*FT + tf + 32*c];
            float a1[4], a2[4];
            #pragma unroll
            for (int i = 0; i < 4; i++) { a1[i] = w1[kk*TM + tm*4 + i]; a2[i] = w2[kk*TM + tm*4 + i]; }
            #pragma unroll
            for (int i = 0; i < 4; i++)
                #pragma unroll
                for (int c = 0; c < 6; c++) {
                    acc1[i][c] = fmaf(a1[i], xv[c], acc1[i][c]);
                    acc2[i][c] = fmaf(a2[i], xv[c], acc2[i][c]);
                }
        }
        __syncthreads();
    }

    // ---- epilogue ----
    float* r1   = sm;            // 6144
    float* r2   = sm + 6144;     // 6144
    float* s0   = sm + 12288;    // 6144
    float* th1  = sm + 18432;    // 512
    float* th2  = sm + 18944;    // 512
    float* th02 = sm + 19456;    // 512

    #pragma unroll
    for (int i = 0; i < 4; i++)
        #pragma unroll
        for (int c = 0; c < 6; c++) {
            int m = tm*4 + i, col = tf + 32*c;
            r1[m*FT + col] = acc1[i][c];
            r2[m*FT + col] = acc2[i][c];
        }
    for (int i = tid; i < FIN*FOUT; i += 256) {
        th1[i] = theta[512 + i];
        float t2 = theta[1024 + i];
        th2[i]  = t2;
        th02[i] = theta[i] - t2;   // theta0 - theta2 (identity term)
    }
    for (int i = tid; i < TM*FT; i += 256) {
        int m = i / FT, ftc = i - m*FT;
        float d = Ab[(size_t)(m0+m)*NN + m0 + m];
        s0[i] = d * xb[(size_t)(m0+m)*FT + ftc];
    }
    __syncthreads();

    float* outb = out + (size_t)b*NN*FOUT*TT;
    for (int idx = tid; idx < TM*FOUT*TT; idx += 256) {
        int m = idx / (FOUT*TT);
        int r = idx - m*(FOUT*TT);
        int o = r / TT, t = r - o*TT;
        float val = 0.f;
        #pragma unroll
        for (int f = 0; f < FIN; f++) {
            int ft = f*TT + t;
            val = fmaf(r1[m*FT + ft], th1[f*FOUT + o], val);
            val = fmaf(r2[m*FT + ft], th2[f*FOUT + o], val);
            val = fmaf(s0[m*FT + ft], th02[f*FOUT + o], val);
        }
        outb[(size_t)(m0+m)*FOUT*TT + r] = fmaxf(val, 0.f);
    }
}

// ---------------------------------------------------------------------------
extern "C" void kernel_launch(void* const* d_in, const int* in_sizes, int n_in,
                              void* d_out, int out_size) {
    const float *x = nullptr, *A = nullptr, *E = nullptr, *theta = nullptr;
    for (int i = 0; i < n_in; i++) {
        switch (in_sizes[i]) {
            case BB*NN*FIN*TT:   x     = (const float*)d_in[i]; break;  // 3145728
            case BB*NN*NN:       A     = (const float*)d_in[i]; break;  // 33554432
            case NN*FIN:         E     = (const float*)d_in[i]; break;  // 32768
            case 3*FIN*FOUT:     theta = (const float*)d_in[i]; break;  // 1536
        }
    }
    float* out = (float*)d_out;

    k_supports<<<NN, 256>>>(E);

    dim3 g2(NN/128, NN/128);
    k_gemm_ss<<<g2, 256>>>();

    const int smem3 = 19968 * (int)sizeof(float);  // 79,872 B
    cudaFuncSetAttribute(k_main, cudaFuncAttributeMaxDynamicSharedMemorySize, smem3);
    dim3 g3(NN/TM, BB);
    k_main<<<g3, 256, smem3>>>(x, A, theta, out);
}

// round 3
// speedup vs baseline: 1.0562x; 1.0562x over previous
#include <cuda_runtime.h>

#define NN   2048
#define FIN  16
#define TT   12
#define FOUT 32
#define BB   8
#define FT   (FIN*TT)   // 192
#define TM   32
#define KT   32

typedef unsigned long long ull;

// scratch: Chebyshev supports and S^2
__device__ float g_S [NN*(size_t)NN];
__device__ float g_S2[NN*(size_t)NN];

// ---- packed f32x2 helpers (Blackwell FFMA2 path) ------------------------
__device__ __forceinline__ ull bcast2(float v) {
    ull r;
    asm("mov.b64 %0, {%1, %1};" : "=l"(r) : "f"(v));
    return r;
}
__device__ __forceinline__ void fma2(ull& d, ull a, ull b) {
    asm("fma.rn.f32x2 %0, %1, %2, %0;" : "+l"(d) : "l"(a), "l"(b));
}

// ---------------------------------------------------------------------------
// Kernel 1: S = softmax(relu(E E^T), axis=1)   (one block per row)
// ---------------------------------------------------------------------------
__global__ __launch_bounds__(256)
void k_supports(const float* __restrict__ E) {
    const int i   = blockIdx.x;
    const int tid = threadIdx.x;
    __shared__ float ei[FIN];
    __shared__ float row[NN];
    __shared__ float red[8];
    __shared__ float bcast0, bcast1;

    if (tid < FIN) ei[tid] = E[i*FIN + tid];
    __syncthreads();

    float lmax = 0.0f;  // relu output >= 0
    for (int j = tid; j < NN; j += 256) {
        const float4* ej = reinterpret_cast<const float4*>(E + (size_t)j*FIN);
        float dot = 0.f;
        #pragma unroll
        for (int q = 0; q < 4; q++) {
            float4 v = ej[q];
            dot += v.x*ei[q*4+0] + v.y*ei[q*4+1] + v.z*ei[q*4+2] + v.w*ei[q*4+3];
        }
        float r = fmaxf(dot, 0.f);
        row[j] = r;
        lmax = fmaxf(lmax, r);
    }
    #pragma unroll
    for (int o = 16; o > 0; o >>= 1) lmax = fmaxf(lmax, __shfl_xor_sync(0xffffffffu, lmax, o));
    if ((tid & 31) == 0) red[tid >> 5] = lmax;
    __syncthreads();
    if (tid == 0) {
        float m = red[0];
        #pragma unroll
        for (int w = 1; w < 8; w++) m = fmaxf(m, red[w]);
        bcast0 = m;
    }
    __syncthreads();
    const float bmax = bcast0;

    float lsum = 0.f;
    for (int j = tid; j < NN; j += 256) {
        float e = expf(row[j] - bmax);
        row[j] = e;
        lsum += e;
    }
    #pragma unroll
    for (int o = 16; o > 0; o >>= 1) lsum += __shfl_xor_sync(0xffffffffu, lsum, o);
    if ((tid & 31) == 0) red[tid >> 5] = lsum;
    __syncthreads();
    if (tid == 0) {
        float s = 0.f;
        #pragma unroll
        for (int w = 0; w < 8; w++) s += red[w];
        bcast1 = 1.0f / s;
    }
    __syncthreads();
    const float inv = bcast1;
    for (int j = tid; j < NN; j += 256)
        g_S[(size_t)i*NN + j] = row[j] * inv;
}

// ---------------------------------------------------------------------------
// Kernel 2: S2 = S @ S   (128x128 tile, 8x8 per thread, packed f32x2)
// ---------------------------------------------------------------------------
__global__ __launch_bounds__(256)
void k_gemm_ss() {
    const float* A = g_S;
    const float* B = g_S;
    float* C = g_S2;
    __shared__ float As[8][132];
    __shared__ float Bs[8][128];

    const int tid = threadIdx.x;
    const int tx = tid & 15, ty = tid >> 4;
    const int i0 = blockIdx.y * 128, j0 = blockIdx.x * 128;

    ull acc[8][4];
    #pragma unroll
    for (int i = 0; i < 8; i++)
        #pragma unroll
        for (int j = 0; j < 4; j++) acc[i][j] = 0ull;

    for (int k0 = 0; k0 < NN; k0 += 8) {
        {   // A tile 128x8, transposed into As
            int row = tid >> 1, q = tid & 1;
            float4 av = *reinterpret_cast<const float4*>(A + (size_t)(i0+row)*NN + k0 + q*4);
            As[q*4+0][row] = av.x; As[q*4+1][row] = av.y;
            As[q*4+2][row] = av.z; As[q*4+3][row] = av.w;
        }
        {   // B tile 8x128
            int row = tid >> 5, c4 = tid & 31;
            float4 bv = *reinterpret_cast<const float4*>(B + (size_t)(k0+row)*NN + j0 + c4*4);
            *reinterpret_cast<float4*>(&Bs[row][c4*4]) = bv;
        }
        __syncthreads();
        #pragma unroll
        for (int k = 0; k < 8; k++) {
            ull bp[4];
            #pragma unroll
            for (int j = 0; j < 4; j++)
                bp[j] = *reinterpret_cast<const ull*>(&Bs[k][tx*8 + 2*j]);
            #pragma unroll
            for (int i = 0; i < 8; i++) {
                ull ab = bcast2(As[k][ty*8 + i]);
                #pragma unroll
                for (int j = 0; j < 4; j++) fma2(acc[i][j], ab, bp[j]);
            }
        }
        __syncthreads();
    }
    #pragma unroll
    for (int i = 0; i < 8; i++) {
        float* crow = C + (size_t)(i0 + ty*8 + i)*NN + j0 + tx*8;
        #pragma unroll
        for (int j = 0; j < 4; j += 2) {
            float2 v0 = *reinterpret_cast<float2*>(&acc[i][j]);
            float2 v1 = *reinterpret_cast<float2*>(&acc[i][j+1]);
            float4 v = make_float4(v0.x, v0.y, v1.x, v1.y);
            *reinterpret_cast<float4*>(crow + 2*j) = v;
        }
    }
}

// ---------------------------------------------------------------------------
// Kernel 3: fused masked dual-GEMM (packed f32x2) + theta epilogue + relu
//   rhs1[m,ft] = sum_n  S[n,m]*A[b,n,m]*x[b,n,ft]
//   rhs2[m,ft] = sum_n 2*S2[n,m]*A[b,n,m]*x[b,n,ft]
//   out[m,o,t] = relu( sum_f rhs1*th1 + rhs2*th2 + A[b,m,m]*x[b,m,f,t]*(th0-th2) )
// ---------------------------------------------------------------------------
__global__ __launch_bounds__(256)
void k_main(const float* __restrict__ x, const float* __restrict__ A,
            const float* __restrict__ theta, float* __restrict__ out) {
    extern __shared__ float sm[];
    float* xs = sm;             // KT*FT = 6144 floats
    float* w1 = sm + 6144;      // KT*TM = 1024
    float* w2 = sm + 7168;      // 1024

    const int b   = blockIdx.y;
    const int m0  = blockIdx.x * TM;
    const int tid = threadIdx.x;
    const int tf  = tid & 31;   // 0..31 (ft lane)
    const int tm  = tid >> 5;   // 0..7  (m group)

    // packed accumulators: i-pairs (m dimension) in the two f32 lanes
    ull acc1[2][6];
    ull acc2[2][6];
    #pragma unroll
    for (int p = 0; p < 2; p++)
        #pragma unroll
        for (int c = 0; c < 6; c++) { acc1[p][c] = 0ull; acc2[p][c] = 0ull; }

    const float* xb = x + (size_t)b*NN*FT;
    const float* Ab = A + (size_t)b*NN*NN;

    for (int n0 = 0; n0 < NN; n0 += KT) {
        // stage x tile (contiguous KT*FT block)
        const float4* x4  = reinterpret_cast<const float4*>(xb + (size_t)n0*FT);
        float4* xs4 = reinterpret_cast<float4*>(xs);
        #pragma unroll
        for (int i = tid; i < KT*FT/4; i += 256) xs4[i] = x4[i];
        // stage masked weight tiles
        #pragma unroll
        for (int i = tid; i < KT*TM; i += 256) {
            int kk = i >> 5;
            int m  = i & 31;
            size_t off = (size_t)(n0 + kk)*NN + m0 + m;
            float a = Ab[off];
            w1[i] = g_S [off] * a;
            w2[i] = 2.0f * g_S2[off] * a;
        }
        __syncthreads();
        #pragma unroll 4
        for (int kk = 0; kk < KT; kk++) {
            ull xv[6];
            #pragma unroll
            for (int c = 0; c < 6; c++) xv[c] = bcast2(xs[kk*FT + tf + 32*c]);
            ull a1p[2], a2p[2];
            #pragma unroll
            for (int p = 0; p < 2; p++) {
                a1p[p] = *reinterpret_cast<const ull*>(&w1[kk*TM + tm*4 + 2*p]);
                a2p[p] = *reinterpret_cast<const ull*>(&w2[kk*TM + tm*4 + 2*p]);
            }
            #pragma unroll
            for (int p = 0; p < 2; p++)
                #pragma unroll
                for (int c = 0; c < 6; c++) {
                    fma2(acc1[p][c], a1p[p], xv[c]);
                    fma2(acc2[p][c], a2p[p], xv[c]);
                }
        }
        __syncthreads();
    }

    // ---- epilogue ----
    float* r1   = sm;            // 6144
    float* r2   = sm + 6144;     // 6144
    float* s0   = sm + 12288;    // 6144
    float* th1  = sm + 18432;    // 512
    float* th2  = sm + 18944;    // 512
    float* th02 = sm + 19456;    // 512

    #pragma unroll
    for (int p = 0; p < 2; p++)
        #pragma unroll
        for (int c = 0; c < 6; c++) {
            int m = tm*4 + 2*p, col = tf + 32*c;
            float2 v1 = *reinterpret_cast<float2*>(&acc1[p][c]);
            float2 v2 = *reinterpret_cast<float2*>(&acc2[p][c]);
            r1[(m+0)*FT + col] = v1.x;
            r1[(m+1)*FT + col] = v1.y;
            r2[(m+0)*FT + col] = v2.x;
            r2[(m+1)*FT + col] = v2.y;
        }
    for (int i = tid; i < FIN*FOUT; i += 256) {
        th1[i] = theta[512 + i];
        float t2 = theta[1024 + i];
        th2[i]  = t2;
        th02[i] = theta[i] - t2;   // theta0 - theta2 (identity term)
    }
    for (int i = tid; i < TM*FT; i += 256) {
        int m = i / FT, ftc = i - m*FT;
        float d = Ab[(size_t)(m0+m)*NN + m0 + m];
        s0[i] = d * xb[(size_t)(m0+m)*FT + ftc];
    }
    __syncthreads();

    float* outb = out + (size_t)b*NN*FOUT*TT;
    for (int idx = tid; idx < TM*FOUT*TT; idx += 256) {
        int m = idx / (FOUT*TT);
        int r = idx - m*(FOUT*TT);
        int o = r / TT, t = r - o*TT;
        float val = 0.f;
        #pragma unroll
        for (int f = 0; f < FIN; f++) {
            int ft = f*TT + t;
            val = fmaf(r1[m*FT + ft], th1[f*FOUT + o], val);
            val = fmaf(r2[m*FT + ft], th2[f*FOUT + o], val);
            val = fmaf(s0[m*FT + ft], th02[f*FOUT + o], val);
        }
        outb[(size_t)(m0+m)*FOUT*TT + r] = fmaxf(val, 0.f);
    }
}

// ---------------------------------------------------------------------------
extern "C" void kernel_launch(void* const* d_in, const int* in_sizes, int n_in,
                              void* d_out, int out_size) {
    const float *x = nullptr, *A = nullptr, *E = nullptr, *theta = nullptr;
    for (int i = 0; i < n_in; i++) {
        switch (in_sizes[i]) {
            case BB*NN*FIN*TT:   x     = (const float*)d_in[i]; break;  // 3145728
            case BB*NN*NN:       A     = (const float*)d_in[i]; break;  // 33554432
            case NN*FIN:         E     = (const float*)d_in[i]; break;  // 32768
            case 3*FIN*FOUT:     theta = (const float*)d_in[i]; break;  // 1536
        }
    }
    float* out = (float*)d_out;

    k_supports<<<NN, 256>>>(E);

    dim3 g2(NN/128, NN/128);
    k_gemm_ss<<<g2, 256>>>();

    const int smem3 = 19968 * (int)sizeof(float);  // 79,872 B
    cudaFuncSetAttribute(k_main, cudaFuncAttributeMaxDynamicSharedMemorySize, smem3);
    dim3 g3(NN/TM, BB);
    k_main<<<g3, 256, smem3>>>(x, A, theta, out);
}

// round 4
// speedup vs baseline: 1.0566x; 1.0004x over previous
#include <cuda_runtime.h>

#define NN   2048
#define FIN  16
#define TT   12
#define FOUT 32
#define BB   8
#define FT   (FIN*TT)   // 192
#define TM   32
#define KT   32

typedef unsigned long long ull;

// scratch: Chebyshev supports and S^2
__device__ float g_S [NN*(size_t)NN];
__device__ float g_S2[NN*(size_t)NN];

// ---- packed f32x2 helpers (Blackwell FFMA2 path) ------------------------
__device__ __forceinline__ ull bcast2(float v) {
    ull r;
    asm("mov.b64 %0, {%1, %1};" : "=l"(r) : "f"(v));
    return r;
}
__device__ __forceinline__ void fma2(ull& d, ull a, ull b) {
    asm("fma.rn.f32x2 %0, %1, %2, %0;" : "+l"(d) : "l"(a), "l"(b));
}

// ---------------------------------------------------------------------------
// Kernel 1: S = softmax(relu(E E^T), axis=1)   (one block per row)
// ---------------------------------------------------------------------------
__global__ __launch_bounds__(256)
void k_supports(const float* __restrict__ E) {
    const int i   = blockIdx.x;
    const int tid = threadIdx.x;
    __shared__ float ei[FIN];
    __shared__ float row[NN];
    __shared__ float red[8];
    __shared__ float bcast0, bcast1;

    if (tid < FIN) ei[tid] = E[i*FIN + tid];
    __syncthreads();

    float lmax = 0.0f;  // relu output >= 0
    for (int j = tid; j < NN; j += 256) {
        const float4* ej = reinterpret_cast<const float4*>(E + (size_t)j*FIN);
        float dot = 0.f;
        #pragma unroll
        for (int q = 0; q < 4; q++) {
            float4 v = ej[q];
            dot += v.x*ei[q*4+0] + v.y*ei[q*4+1] + v.z*ei[q*4+2] + v.w*ei[q*4+3];
        }
        float r = fmaxf(dot, 0.f);
        row[j] = r;
        lmax = fmaxf(lmax, r);
    }
    #pragma unroll
    for (int o = 16; o > 0; o >>= 1) lmax = fmaxf(lmax, __shfl_xor_sync(0xffffffffu, lmax, o));
    if ((tid & 31) == 0) red[tid >> 5] = lmax;
    __syncthreads();
    if (tid == 0) {
        float m = red[0];
        #pragma unroll
        for (int w = 1; w < 8; w++) m = fmaxf(m, red[w]);
        bcast0 = m;
    }
    __syncthreads();
    const float bmax = bcast0;

    float lsum = 0.f;
    for (int j = tid; j < NN; j += 256) {
        float e = expf(row[j] - bmax);
        row[j] = e;
        lsum += e;
    }
    #pragma unroll
    for (int o = 16; o > 0; o >>= 1) lsum += __shfl_xor_sync(0xffffffffu, lsum, o);
    if ((tid & 31) == 0) red[tid >> 5] = lsum;
    __syncthreads();
    if (tid == 0) {
        float s = 0.f;
        #pragma unroll
        for (int w = 0; w < 8; w++) s += red[w];
        bcast1 = 1.0f / s;
    }
    __syncthreads();
    const float inv = bcast1;
    for (int j = tid; j < NN; j += 256)
        g_S[(size_t)i*NN + j] = row[j] * inv;
}

// ---------------------------------------------------------------------------
// Kernel 2: S2 = S @ S   (128x128 tile, 8x8 per thread, packed f32x2)
// ---------------------------------------------------------------------------
__global__ __launch_bounds__(256)
void k_gemm_ss() {
    const float* A = g_S;
    const float* B = g_S;
    float* C = g_S2;
    __shared__ float As[8][132];
    __shared__ float Bs[8][128];

    const int tid = threadIdx.x;
    const int tx = tid & 15, ty = tid >> 4;
    const int i0 = blockIdx.y * 128, j0 = blockIdx.x * 128;

    ull acc[8][4];
    #pragma unroll
    for (int i = 0; i < 8; i++)
        #pragma unroll
        for (int j = 0; j < 4; j++) acc[i][j] = 0ull;

    for (int k0 = 0; k0 < NN; k0 += 8) {
        {   // A tile 128x8, transposed into As
            int row = tid >> 1, q = tid & 1;
            float4 av = *reinterpret_cast<const float4*>(A + (size_t)(i0+row)*NN + k0 + q*4);
            As[q*4+0][row] = av.x; As[q*4+1][row] = av.y;
            As[q*4+2][row] = av.z; As[q*4+3][row] = av.w;
        }
        {   // B tile 8x128
            int row = tid >> 5, c4 = tid & 31;
            float4 bv = *reinterpret_cast<const float4*>(B + (size_t)(k0+row)*NN + j0 + c4*4);
            *reinterpret_cast<float4*>(&Bs[row][c4*4]) = bv;
        }
        __syncthreads();
        #pragma unroll
        for (int k = 0; k < 8; k++) {
            ull bp[4];
            #pragma unroll
            for (int j = 0; j < 4; j++)
                bp[j] = *reinterpret_cast<const ull*>(&Bs[k][tx*8 + 2*j]);
            #pragma unroll
            for (int i = 0; i < 8; i++) {
                ull ab = bcast2(As[k][ty*8 + i]);
                #pragma unroll
                for (int j = 0; j < 4; j++) fma2(acc[i][j], ab, bp[j]);
            }
        }
        __syncthreads();
    }
    #pragma unroll
    for (int i = 0; i < 8; i++) {
        float* crow = C + (size_t)(i0 + ty*8 + i)*NN + j0 + tx*8;
        #pragma unroll
        for (int j = 0; j < 4; j += 2) {
            float2 v0 = *reinterpret_cast<float2*>(&acc[i][j]);
            float2 v1 = *reinterpret_cast<float2*>(&acc[i][j+1]);
            float4 v = make_float4(v0.x, v0.y, v1.x, v1.y);
            *reinterpret_cast<float4*>(crow + 2*j) = v;
        }
    }
}

// ---------------------------------------------------------------------------
// Kernel 3: fused masked dual-GEMM (packed f32x2) + theta epilogue + relu
//   rhs1[m,ft] = sum_n  S[n,m]*A[b,n,m]*x[b,n,ft]
//   rhs2[m,ft] = sum_n 2*S2[n,m]*A[b,n,m]*x[b,n,ft]
//   out[m,o,t] = relu( sum_f rhs1*th1 + rhs2*th2 + A[b,m,m]*x[b,m,f,t]*(th0-th2) )
// ---------------------------------------------------------------------------
__global__ __launch_bounds__(256)
void k_main(const float* __restrict__ x, const float* __restrict__ A,
            const float* __restrict__ theta, float* __restrict__ out) {
    extern __shared__ float sm[];
    float* xs = sm;             // KT*FT = 6144 floats
    float* w1 = sm + 6144;      // KT*TM = 1024
    float* w2 = sm + 7168;      // 1024

    const int b   = blockIdx.y;
    const int m0  = blockIdx.x * TM;
    const int tid = threadIdx.x;
    const int tf  = tid & 31;   // 0..31 (ft lane)
    const int tm  = tid >> 5;   // 0..7  (m group)

    // packed accumulators: i-pairs (m dimension) in the two f32 lanes
    ull acc1[2][6];
    ull acc2[2][6];
    #pragma unroll
    for (int p = 0; p < 2; p++)
        #pragma unroll
        for (int c = 0; c < 6; c++) { acc1[p][c] = 0ull; acc2[p][c] = 0ull; }

    const float* xb = x + (size_t)b*NN*FT;
    const float* Ab = A + (size_t)b*NN*NN;

    for (int n0 = 0; n0 < NN; n0 += KT) {
        // stage x tile (contiguous KT*FT block)
        const float4* x4  = reinterpret_cast<const float4*>(xb + (size_t)n0*FT);
        float4* xs4 = reinterpret_cast<float4*>(xs);
        #pragma unroll
        for (int i = tid; i < KT*FT/4; i += 256) xs4[i] = x4[i];
        // stage masked weight tiles
        #pragma unroll
        for (int i = tid; i < KT*TM; i += 256) {
            int kk = i >> 5;
            int m  = i & 31;
            size_t off = (size_t)(n0 + kk)*NN + m0 + m;
            float a = Ab[off];
            w1[i] = g_S [off] * a;
            w2[i] = 2.0f * g_S2[off] * a;
        }
        __syncthreads();
        #pragma unroll 4
        for (int kk = 0; kk < KT; kk++) {
            ull xv[6];
            #pragma unroll
            for (int c = 0; c < 6; c++) xv[c] = bcast2(xs[kk*FT + tf + 32*c]);
            ull a1p[2], a2p[2];
            #pragma unroll
            for (int p = 0; p < 2; p++) {
                a1p[p] = *reinterpret_cast<const ull*>(&w1[kk*TM + tm*4 + 2*p]);
                a2p[p] = *reinterpret_cast<const ull*>(&w2[kk*TM + tm*4 + 2*p]);
            }
            #pragma unroll
            for (int p = 0; p < 2; p++)
                #pragma unroll
                for (int c = 0; c < 6; c++) {
                    fma2(acc1[p][c], a1p[p], xv[c]);
                    fma2(acc2[p][c], a2p[p], xv[c]);
                }
        }
        __syncthreads();
    }

    // ---- epilogue ----
    float* r1   = sm;            // 6144
    float* r2   = sm + 6144;     // 6144
    float* s0   = sm + 12288;    // 6144
    float* th1  = sm + 18432;    // 512
    float* th2  = sm + 18944;    // 512
    float* th02 = sm + 19456;    // 512

    #pragma unroll
    for (int p = 0; p < 2; p++)
        #pragma unroll
        for (int c = 0; c < 6; c++) {
            int m = tm*4 + 2*p, col = tf + 32*c;
            float2 v1 = *reinterpret_cast<float2*>(&acc1[p][c]);
            float2 v2 = *reinterpret_cast<float2*>(&acc2[p][c]);
            r1[(m+0)*FT + col] = v1.x;
            r1[(m+1)*FT + col] = v1.y;
            r2[(m+0)*FT + col] = v2.x;
            r2[(m+1)*FT + col] = v2.y;
        }
    for (int i = tid; i < FIN*FOUT; i += 256) {
        th1[i] = theta[512 + i];
        float t2 = theta[1024 + i];
        th2[i]  = t2;
        th02[i] = theta[i] - t2;   // theta0 - theta2 (identity term)
    }
    for (int i = tid; i < TM*FT; i += 256) {
        int m = i / FT, ftc = i - m*FT;
        float d = Ab[(size_t)(m0+m)*NN + m0 + m];
        s0[i] = d * xb[(size_t)(m0+m)*FT + ftc];
    }
    __syncthreads();

    float* outb = out + (size_t)b*NN*FOUT*TT;
    for (int idx = tid; idx < TM*FOUT*TT; idx += 256) {
        int m = idx / (FOUT*TT);
        int r = idx - m*(FOUT*TT);
        int o = r / TT, t = r - o*TT;
        float val = 0.f;
        #pragma unroll
        for (int f = 0; f < FIN; f++) {
            int ft = f*TT + t;
            val = fmaf(r1[m*FT + ft], th1[f*FOUT + o], val);
            val = fmaf(r2[m*FT + ft], th2[f*FOUT + o], val);
            val = fmaf(s0[m*FT + ft], th02[f*FOUT + o], val);
        }
        outb[(size_t)(m0+m)*FOUT*TT + r] = fmaxf(val, 0.f);
    }
}

// ---------------------------------------------------------------------------
extern "C" void kernel_launch(void* const* d_in, const int* in_sizes, int n_in,
                              void* d_out, int out_size) {
    const float *x = nullptr, *A = nullptr, *E = nullptr, *theta = nullptr;
    for (int i = 0; i < n_in; i++) {
        switch (in_sizes[i]) {
            case BB*NN*FIN*TT:   x     = (const float*)d_in[i]; break;  // 3145728
            case BB*NN*NN:       A     = (const float*)d_in[i]; break;  // 33554432
            case NN*FIN:         E     = (const float*)d_in[i]; break;  // 32768
            case 3*FIN*FOUT:     theta = (const float*)d_in[i]; break;  // 1536
        }
    }
    float* out = (float*)d_out;

    k_supports<<<NN, 256>>>(E);

    dim3 g2(NN/128, NN/128);
    k_gemm_ss<<<g2, 256>>>();

    const int smem3 = 19968 * (int)sizeof(float);  // 79,872 B
    cudaFuncSetAttribute(k_main, cudaFuncAttributeMaxDynamicSharedMemorySize, smem3);
    dim3 g3(NN/TM, BB);
    k_main<<<g3, 256, smem3>>>(x, A, theta, out);
}

// round 6
// speedup vs baseline: 1.3624x; 1.2895x over previous
#include <cuda_runtime.h>
#include <cuda_bf16.h>
#include <cstdint>

#define NN   2048
#define FIN  16
#define TT   12
#define FOUT 32
#define BB   8
#define FT   192
#define KC   32      // k-chunk
#define WSTR 40      // padded row stride in halves (80 B)

typedef unsigned int u32;

// ------------------------------ scratch globals ------------------------------
__device__ float g_S  [NN*(size_t)NN];
__device__ float g_ST [NN*(size_t)NN];
__device__ float g_S2T[NN*(size_t)NN];
__device__ float g_AT [BB*(size_t)NN*NN];
__device__ __nv_bfloat16 g_Shi [NN*(size_t)NN];
__device__ __nv_bfloat16 g_Slo [NN*(size_t)NN];
__device__ __nv_bfloat16 g_SThi[NN*(size_t)NN];
__device__ __nv_bfloat16 g_STlo[NN*(size_t)NN];
__device__ __nv_bfloat16 g_xThi[BB*(size_t)FT*NN];
__device__ __nv_bfloat16 g_xTlo[BB*(size_t)FT*NN];
__device__ float g_r1[BB*(size_t)NN*FT];
__device__ float g_r2[BB*(size_t)NN*FT];

// ------------------------------ helpers ------------------------------
__device__ __forceinline__ u32 smem_u32(const void* p) {
    u32 a;
    asm("{ .reg .u64 t; cvta.to.shared.u64 t, %1; cvt.u32.u64 %0, t; }" : "=r"(a) : "l"(p));
    return a;
}
__device__ __forceinline__ void ldsm_x4(u32* r, u32 addr) {
    asm volatile("ldmatrix.sync.aligned.m8n8.x4.shared.b16 {%0,%1,%2,%3}, [%4];"
        : "=r"(r[0]), "=r"(r[1]), "=r"(r[2]), "=r"(r[3]) : "r"(addr));
}
__device__ __forceinline__ void ldsm_x2(u32* r, u32 addr) {
    asm volatile("ldmatrix.sync.aligned.m8n8.x2.shared.b16 {%0,%1}, [%2];"
        : "=r"(r[0]), "=r"(r[1]) : "r"(addr));
}
__device__ __forceinline__ void mma_bf16(float* d, const u32* a, const u32* b) {
    asm volatile("mma.sync.aligned.m16n8k16.row.col.f32.bf16.bf16.f32 "
        "{%0,%1,%2,%3}, {%4,%5,%6,%7}, {%8,%9}, {%0,%1,%2,%3};"
        : "+f"(d[0]), "+f"(d[1]), "+f"(d[2]), "+f"(d[3])
        : "r"(a[0]), "r"(a[1]), "r"(a[2]), "r"(a[3]), "r"(b[0]), "r"(b[1]));
}
__device__ __forceinline__ void split_bf16(float v, __nv_bfloat16& h, __nv_bfloat16& l) {
    h = __float2bfloat16(v);
    l = __float2bfloat16(v - __bfloat162float(h));
}

// ---------------------------------------------------------------------------
// Kernel 1: S = softmax(relu(E E^T), axis=1)
// ---------------------------------------------------------------------------
__global__ __launch_bounds__(256)
void k_supports(const float* __restrict__ E) {
    const int i   = blockIdx.x;
    const int tid = threadIdx.x;
    __shared__ float ei[FIN];
    __shared__ float row[NN];
    __shared__ float red[8];
    __shared__ float bc0, bc1;

    if (tid < FIN) ei[tid] = E[i*FIN + tid];
    __syncthreads();

    float lmax = 0.0f;
    for (int j = tid; j < NN; j += 256) {
        const float4* ej = reinterpret_cast<const float4*>(E + (size_t)j*FIN);
        float dot = 0.f;
        #pragma unroll
        for (int q = 0; q < 4; q++) {
            float4 v = ej[q];
            dot += v.x*ei[q*4+0] + v.y*ei[q*4+1] + v.z*ei[q*4+2] + v.w*ei[q*4+3];
        }
        float r = fmaxf(dot, 0.f);
        row[j] = r;
        lmax = fmaxf(lmax, r);
    }
    #pragma unroll
    for (int o = 16; o > 0; o >>= 1) lmax = fmaxf(lmax, __shfl_xor_sync(0xffffffffu, lmax, o));
    if ((tid & 31) == 0) red[tid >> 5] = lmax;
    __syncthreads();
    if (tid == 0) {
        float m = red[0];
        #pragma unroll
        for (int w = 1; w < 8; w++) m = fmaxf(m, red[w]);
        bc0 = m;
    }
    __syncthreads();
    const float bmax = bc0;

    float lsum = 0.f;
    for (int j = tid; j < NN; j += 256) {
        float e = expf(row[j] - bmax);
        row[j] = e;
        lsum += e;
    }
    #pragma unroll
    for (int o = 16; o > 0; o >>= 1) lsum += __shfl_xor_sync(0xffffffffu, lsum, o);
    if ((tid & 31) == 0) red[tid >> 5] = lsum;
    __syncthreads();
    if (tid == 0) {
        float s = 0.f;
        #pragma unroll
        for (int w = 0; w < 8; w++) s += red[w];
        bc1 = 1.0f / s;
    }
    __syncthreads();
    const float inv = bc1;
    for (int j = tid; j < NN; j += 256)
        g_S[(size_t)i*NN + j] = row[j] * inv;
}

// ---------------------------------------------------------------------------
// Kernel 2: S -> Shi/Slo (same layout) and ST/SThi/STlo (transposed)
// ---------------------------------------------------------------------------
__global__ __launch_bounds__(256)
void k_prepS() {
    __shared__ float t[64][65];
    const int tid = threadIdx.x;
    const int i0 = blockIdx.y*64, j0 = blockIdx.x*64;

    for (int idx = tid; idx < 1024; idx += 256) {
        int r = idx >> 4, q = idx & 15;
        float4 v = *reinterpret_cast<const float4*>(&g_S[(size_t)(i0+r)*NN + j0 + q*4]);
        t[r][q*4+0] = v.x; t[r][q*4+1] = v.y; t[r][q*4+2] = v.z; t[r][q*4+3] = v.w;
    }
    __syncthreads();
    // straight split
    for (int idx = tid; idx < 4096; idx += 256) {
        int r = idx >> 6, c = idx & 63;
        __nv_bfloat16 h, l; split_bf16(t[r][c], h, l);
        size_t o = (size_t)(i0+r)*NN + j0 + c;
        g_Shi[o] = h; g_Slo[o] = l;
    }
    // transposed copy + split
    for (int idx = tid; idx < 4096; idx += 256) {
        int c = idx >> 6, r = idx & 63;
        float v = t[r][c];
        __nv_bfloat16 h, l; split_bf16(v, h, l);
        size_t o = (size_t)(j0+c)*NN + i0 + r;
        g_ST[o] = v; g_SThi[o] = h; g_STlo[o] = l;
    }
}

// ---------------------------------------------------------------------------
// Kernel 3: xT[b][ft][n] hi/lo split
// ---------------------------------------------------------------------------
__global__ __launch_bounds__(256)
void k_prepx(const float* __restrict__ x) {
    __shared__ float t[FT][33];
    const int tid = threadIdx.x;
    const int b  = blockIdx.y;
    const int n0 = blockIdx.x*32;
    const float* xb = x + (size_t)b*NN*FT;

    for (int idx = tid; idx < 32*48; idx += 256) {
        int r = idx / 48, q = idx % 48;
        float4 v = *reinterpret_cast<const float4*>(&xb[(size_t)(n0+r)*FT + q*4]);
        t[q*4+0][r] = v.x; t[q*4+1][r] = v.y; t[q*4+2][r] = v.z; t[q*4+3][r] = v.w;
    }
    __syncthreads();
    for (int idx = tid; idx < FT*32; idx += 256) {
        int ft = idx >> 5, n = idx & 31;
        __nv_bfloat16 h, l; split_bf16(t[ft][n], h, l);
        size_t o = ((size_t)b*FT + ft)*NN + n0 + n;
        g_xThi[o] = h; g_xTlo[o] = l;
    }
}

// ---------------------------------------------------------------------------
// Kernel 4: AT[b][m][n] = A[b][n][m]
// ---------------------------------------------------------------------------
__global__ __launch_bounds__(256)
void k_transA(const float* __restrict__ A) {
    __shared__ float t[64][65];
    const int tid = threadIdx.x;
    const int b  = blockIdx.z;
    const int m0 = blockIdx.x*64, n0 = blockIdx.y*64;
    const float* Ab = A + (size_t)b*NN*NN;
    float* ATb = g_AT + (size_t)b*NN*NN;

    for (int idx = tid; idx < 1024; idx += 256) {
        int r = idx >> 4, q = idx & 15;
        float4 v = *reinterpret_cast<const float4*>(&Ab[(size_t)(n0+r)*NN + m0 + q*4]);
        t[r][q*4+0] = v.x; t[r][q*4+1] = v.y; t[r][q*4+2] = v.z; t[r][q*4+3] = v.w;
    }
    __syncthreads();
    for (int idx = tid; idx < 4096; idx += 256) {
        int c = idx >> 6, r = idx & 63;
        ATb[(size_t)(m0+c)*NN + n0 + r] = t[r][c];
    }
}

// ---------------------------------------------------------------------------
// Kernel 5: S2T[i][j] = sum_k ST[i,k]*S[j,k]  (3-pass bf16 mma.sync)
// CTA: 128(i) x 128(j), 8 warps (2x4), warp tile 64x32
// ---------------------------------------------------------------------------
__global__ __launch_bounds__(256)
void k_s2() {
    __shared__ __align__(16) __nv_bfloat16 sh[4*128*WSTR];  // ATH,ATL,BH,BL
    const int ATH = 0, ATL = 128*WSTR, BH = 2*128*WSTR, BL = 3*128*WSTR;

    const int tid = threadIdx.x, w = tid >> 5, lane = tid & 31;
    const int wm = w >> 2, wn = w & 3;
    const int i0 = blockIdx.y*128, j0 = blockIdx.x*128;
    const u32 sb = smem_u32(sh);

    float d[4][4][4];
    #pragma unroll
    for (int mt = 0; mt < 4; mt++)
        #pragma unroll
        for (int nt = 0; nt < 4; nt++)
            #pragma unroll
            for (int e = 0; e < 4; e++) d[mt][nt][e] = 0.f;

    for (int n0 = 0; n0 < NN; n0 += KC) {
        for (int idx = tid; idx < 2048; idx += 256) {
            int arr = idx >> 9, i = idx & 511, row = i >> 2, q = i & 3;
            const __nv_bfloat16* src;
            int grow, dbase;
            if      (arr == 0) { src = g_SThi; grow = i0 + row; dbase = ATH; }
            else if (arr == 1) { src = g_STlo; grow = i0 + row; dbase = ATL; }
            else if (arr == 2) { src = g_Shi;  grow = j0 + row; dbase = BH;  }
            else               { src = g_Slo;  grow = j0 + row; dbase = BL;  }
            uint4 v = *reinterpret_cast<const uint4*>(src + (size_t)grow*NN + n0 + q*8);
            *reinterpret_cast<uint4*>(reinterpret_cast<char*>(sh) + (dbase + row*WSTR + q*8)*2) = v;
        }
        __syncthreads();
        #pragma unroll
        for (int ks = 0; ks < 2; ks++) {
            u32 ah[4][4], al[4][4], bh[4][2], bl[4][2];
            const int arow = wm*64 + (lane & 15);
            const int acol = ks*16 + (lane >> 4)*8;
            #pragma unroll
            for (int mt = 0; mt < 4; mt++) {
                u32 ad = sb + (u32)(((arow + mt*16)*WSTR + acol)*2);
                ldsm_x4(ah[mt], ad + ATH*2);
                ldsm_x4(al[mt], ad + ATL*2);
            }
            const int brow = wn*32 + (lane & 7);
            const int bcol = ks*16 + ((lane >> 3) & 1)*8;
            #pragma unroll
            for (int nt = 0; nt < 4; nt++) {
                u32 bd = sb + (u32)(((brow + nt*8)*WSTR + bcol)*2);
                ldsm_x2(bh[nt], bd + BH*2);
                ldsm_x2(bl[nt], bd + BL*2);
            }
            #pragma unroll
            for (int mt = 0; mt < 4; mt++)
                #pragma unroll
                for (int nt = 0; nt < 4; nt++) {
                    mma_bf16(d[mt][nt], ah[mt], bh[nt]);
                    mma_bf16(d[mt][nt], ah[mt], bl[nt]);
                    mma_bf16(d[mt][nt], al[mt], bh[nt]);
                }
        }
        __syncthreads();
    }
    #pragma unroll
    for (int mt = 0; mt < 4; mt++)
        #pragma unroll
        for (int nt = 0; nt < 4; nt++) {
            int row = i0 + wm*64 + mt*16 + (lane >> 2);
            int col = j0 + wn*32 + nt*8 + (lane & 3)*2;
            *reinterpret_cast<float2*>(&g_S2T[(size_t)row*NN + col]) =
                make_float2(d[mt][nt][0], d[mt][nt][1]);
            *reinterpret_cast<float2*>(&g_S2T[(size_t)(row+8)*NN + col]) =
                make_float2(d[mt][nt][2], d[mt][nt][3]);
        }
}

// ---------------------------------------------------------------------------
// Kernel 6: masked dual-GEMM via mma.sync
//   W rows 0-127:  W1[m,n] = ST[m,n]*AT[b,m,n]        -> r1
//   W rows 128-255: W2[m,n] = 2*S2T[m,n]*AT[b,m,n]    -> r2
//   B: xT[b][ft][n], ft-half selected by blockIdx.y
// CTA: 512 threads, M=256, N=96, 16 warps (4x4), warp tile 64x24
// ---------------------------------------------------------------------------
#define KM_WHI 0
#define KM_WLO (256*WSTR)
#define KM_XHI (512*WSTR)
#define KM_XLO (512*WSTR + 96*WSTR)
#define KM_HALVES (512*WSTR + 192*WSTR)

__global__ __launch_bounds__(512)
void k_main() {
    extern __shared__ __align__(16) __nv_bfloat16 sh[];
    const int tid = threadIdx.x, w = tid >> 5, lane = tid & 31;
    const int wm = w >> 2, wn = w & 3;
    const int m0 = blockIdx.x*128;
    const int nh = blockIdx.y;          // ft half
    const int b  = blockIdx.z;
    const u32 sb = smem_u32(sh);

    const float* ATb = g_AT + (size_t)b*NN*NN;
    const __nv_bfloat16* xh = g_xThi + ((size_t)b*FT + nh*96)*NN;
    const __nv_bfloat16* xl = g_xTlo + ((size_t)b*FT + nh*96)*NN;

    float d[4][3][4];
    #pragma unroll
    for (int mt = 0; mt < 4; mt++)
        #pragma unroll
        for (int nt = 0; nt < 3; nt++)
            #pragma unroll
            for (int e = 0; e < 4; e++) d[mt][nt][e] = 0.f;

    for (int n0 = 0; n0 < NN; n0 += KC) {
        // stage x (96 rows x 32 halves, hi+lo)
        for (int idx = tid; idx < 768; idx += 512) {
            int sel = idx >= 384;
            int i = idx - sel*384;
            int row = i >> 2, q = i & 3;
            const __nv_bfloat16* src = sel ? xl : xh;
            uint4 v = *reinterpret_cast<const uint4*>(src + (size_t)row*NN + n0 + q*8);
            int dbase = (sel ? KM_XLO : KM_XHI) + row*WSTR + q*8;
            *reinterpret_cast<uint4*>(reinterpret_cast<char*>(sh) + dbase*2) = v;
        }
        // build masked W (256 rows x 32), float2 wide
        for (int idx = tid; idx < 4096; idx += 512) {
            int mrow = idx >> 4, c = (idx & 15)*2;
            int mg = m0 + (mrow & 127);
            size_t go = (size_t)mg*NN + n0 + c;
            float2 at = *reinterpret_cast<const float2*>(ATb + go);
            float2 s  = (mrow < 128) ? *reinterpret_cast<const float2*>(g_ST + go)
                                     : *reinterpret_cast<const float2*>(g_S2T + go);
            float sc = (mrow < 128) ? 1.f : 2.f;
            float wx = s.x*at.x*sc, wy = s.y*at.y*sc;
            __nv_bfloat16 hx, lx, hy, ly;
            split_bf16(wx, hx, lx); split_bf16(wy, hy, ly);
            char* base = reinterpret_cast<char*>(sh);
            *reinterpret_cast<__nv_bfloat162*>(base + (KM_WHI + mrow*WSTR + c)*2) = __nv_bfloat162(hx, hy);
            *reinterpret_cast<__nv_bfloat162*>(base + (KM_WLO + mrow*WSTR + c)*2) = __nv_bfloat162(lx, ly);
        }
        __syncthreads();
        #pragma unroll
        for (int ks = 0; ks < 2; ks++) {
            u32 ah[4][4], al[4][4], bh[3][2], bl[3][2];
            const int arow = wm*64 + (lane & 15);
            const int acol = ks*16 + (lane >> 4)*8;
            #pragma unroll
            for (int mt = 0; mt < 4; mt++) {
                u32 ad = sb + (u32)(((arow + mt*16)*WSTR + acol)*2);
                ldsm_x4(ah[mt], ad + KM_WHI*2);
                ldsm_x4(al[mt], ad + KM_WLO*2);
            }
            const int brow = wn*24 + (lane & 7);
            const int bcol = ks*16 + ((lane >> 3) & 1)*8;
            #pragma unroll
            for (int nt = 0; nt < 3; nt++) {
                u32 bd = sb + (u32)(((brow + nt*8)*WSTR + bcol)*2);
                ldsm_x2(bh[nt], bd + KM_XHI*2);
                ldsm_x2(bl[nt], bd + KM_XLO*2);
            }
            #pragma unroll
            for (int mt = 0; mt < 4; mt++)
                #pragma unroll
                for (int nt = 0; nt < 3; nt++) {
                    mma_bf16(d[mt][nt], ah[mt], bh[nt]);
                    mma_bf16(d[mt][nt], ah[mt], bl[nt]);
                    mma_bf16(d[mt][nt], al[mt], bh[nt]);
                }
        }
        __syncthreads();
    }
    // epilogue: write r1 / r2
    #pragma unroll
    for (int mt = 0; mt < 4; mt++)
        #pragma unroll
        for (int nt = 0; nt < 3; nt++) {
            int mrow = wm*64 + mt*16 + (lane >> 2);
            int col  = nh*96 + wn*24 + nt*8 + (lane & 3)*2;
            float* base = (mrow < 128) ? g_r1 : g_r2;
            size_t off = ((size_t)b*NN + m0 + (mrow & 127))*FT + col;
            *reinterpret_cast<float2*>(base + off) = make_float2(d[mt][nt][0], d[mt][nt][1]);
            *reinterpret_cast<float2*>(base + off + 8*FT) = make_float2(d[mt][nt][2], d[mt][nt][3]);
        }
}

// ---------------------------------------------------------------------------
// Kernel 7: theta contraction + diagonal identity term + relu
// ---------------------------------------------------------------------------
__global__ __launch_bounds__(256)
void k_theta(const float* __restrict__ x, const float* __restrict__ A,
             const float* __restrict__ theta, float* __restrict__ out) {
    extern __shared__ float smf[];
    float* r1   = smf;             // 32*192
    float* r2   = smf + 6144;
    float* s0   = smf + 12288;
    float* th1  = smf + 18432;
    float* th2  = smf + 18944;
    float* th02 = smf + 19456;

    const int b   = blockIdx.y;
    const int m0  = blockIdx.x * 32;
    const int tid = threadIdx.x;
    const float* xb = x + (size_t)b*NN*FT;
    const float* Ab = A + (size_t)b*NN*NN;

    for (int i = tid; i < 1536; i += 256) {
        reinterpret_cast<float4*>(r1)[i] =
            reinterpret_cast<const float4*>(g_r1 + ((size_t)b*NN + m0)*FT)[i];
        reinterpret_cast<float4*>(r2)[i] =
            reinterpret_cast<const float4*>(g_r2 + ((size_t)b*NN + m0)*FT)[i];
    }
    for (int i = tid; i < FIN*FOUT; i += 256) {
        th1[i] = theta[512 + i];
        float t2 = theta[1024 + i];
        th2[i]  = t2;
        th02[i] = theta[i] - t2;
    }
    for (int i = tid; i < 32*FT; i += 256) {
        int m = i / FT, ftc = i - m*FT;
        float dg = Ab[(size_t)(m0+m)*NN + m0 + m];
        s0[i] = dg * xb[(size_t)(m0+m)*FT + ftc];
    }
    __syncthreads();

    float* outb = out + (size_t)b*NN*FOUT*TT;
    for (int idx = tid; idx < 32*FOUT*TT; idx += 256) {
        int m = idx / (FOUT*TT);
        int r = idx - m*(FOUT*TT);
        int o = r / TT, t = r - o*TT;
        float val = 0.f;
        #pragma unroll
        for (int f = 0; f < FIN; f++) {
            int ft = f*TT + t;
            val = fmaf(r1[m*FT + ft], th1[f*FOUT + o], val);
            val = fmaf(r2[m*FT + ft], th2[f*FOUT + o], val);
            val = fmaf(s0[m*FT + ft], th02[f*FOUT + o], val);
        }
        outb[(size_t)(m0+m)*FOUT*TT + r] = fmaxf(val, 0.f);
    }
}

// ---------------------------------------------------------------------------
extern "C" void kernel_launch(void* const* d_in, const int* in_sizes, int n_in,
                              void* d_out, int out_size) {
    const float *x = nullptr, *A = nullptr, *E = nullptr, *theta = nullptr;
    for (int i = 0; i < n_in; i++) {
        switch (in_sizes[i]) {
            case BB*NN*FIN*TT:   x     = (const float*)d_in[i]; break;
            case BB*NN*NN:       A     = (const float*)d_in[i]; break;
            case NN*FIN:         E     = (const float*)d_in[i]; break;
            case 3*FIN*FOUT:     theta = (const float*)d_in[i]; break;
        }
    }
    float* out = (float*)d_out;

    k_supports<<<NN, 256>>>(E);
    k_prepS<<<dim3(32, 32), 256>>>();
    k_prepx<<<dim3(64, BB), 256>>>(x);
    k_transA<<<dim3(32, 32, BB), 256>>>(A);

    k_s2<<<dim3(16, 16), 256>>>();

    const int km_smem = KM_HALVES * 2;   // 56,320 B
    cudaFuncSetAttribute(k_main, cudaFuncAttributeMaxDynamicSharedMemorySize, km_smem);
    k_main<<<dim3(16, 2, BB), 512, km_smem>>>();

    const int smem_th = 19968 * (int)sizeof(float);
    cudaFuncSetAttribute(k_theta, cudaFuncAttributeMaxDynamicSharedMemorySize, smem_th);
    k_theta<<<dim3(NN/32, BB), 256, smem_th>>>(x, A, theta, out);
}

// round 7
// speedup vs baseline: 2.1232x; 1.5585x over previous
#include <cuda_runtime.h>
#include <cuda_bf16.h>
#include <cstdint>

#define NN   2048
#define FIN  16
#define TT   12
#define FOUT 32
#define BB   8
#define FT   192
#define WSTR 40      // k_main padded row stride in halves (80 B, conflict-free ldmatrix)
#define S2STR 72     // k_s2 padded row stride in halves (144 B, conflict-free ldmatrix)

typedef unsigned int u32;

// ------------------------------ scratch globals ------------------------------
__device__ float g_S  [NN*(size_t)NN];
__device__ float g_ST [NN*(size_t)NN];
__device__ float g_S2T[NN*(size_t)NN];
__device__ __nv_bfloat16 g_Shi [NN*(size_t)NN];
__device__ __nv_bfloat16 g_Slo [NN*(size_t)NN];
__device__ __nv_bfloat16 g_SThi[NN*(size_t)NN];
__device__ __nv_bfloat16 g_STlo[NN*(size_t)NN];
__device__ __nv_bfloat16 g_xThi[BB*(size_t)FT*NN];
__device__ __nv_bfloat16 g_xTlo[BB*(size_t)FT*NN];
__device__ float g_r1[BB*(size_t)NN*FT];
__device__ float g_r2[BB*(size_t)NN*FT];

// ------------------------------ helpers ------------------------------
__device__ __forceinline__ u32 smem_u32(const void* p) {
    u32 a;
    asm("{ .reg .u64 t; cvta.to.shared.u64 t, %1; cvt.u32.u64 %0, t; }" : "=r"(a) : "l"(p));
    return a;
}
__device__ __forceinline__ void cp16(u32 dst, const void* src) {
    asm volatile("cp.async.cg.shared.global [%0], [%1], 16;" :: "r"(dst), "l"(src));
}
#define CP_COMMIT() asm volatile("cp.async.commit_group;" ::: "memory")
#define CP_WAIT(n)  asm volatile("cp.async.wait_group %0;" :: "n"(n) : "memory")

__device__ __forceinline__ void ldsm_x4(u32* r, u32 addr) {
    asm volatile("ldmatrix.sync.aligned.m8n8.x4.shared.b16 {%0,%1,%2,%3}, [%4];"
        : "=r"(r[0]), "=r"(r[1]), "=r"(r[2]), "=r"(r[3]) : "r"(addr));
}
__device__ __forceinline__ void ldsm_x2(u32* r, u32 addr) {
    asm volatile("ldmatrix.sync.aligned.m8n8.x2.shared.b16 {%0,%1}, [%2];"
        : "=r"(r[0]), "=r"(r[1]) : "r"(addr));
}
__device__ __forceinline__ void mma_bf16(float* d, const u32* a, const u32* b) {
    asm volatile("mma.sync.aligned.m16n8k16.row.col.f32.bf16.bf16.f32 "
        "{%0,%1,%2,%3}, {%4,%5,%6,%7}, {%8,%9}, {%0,%1,%2,%3};"
        : "+f"(d[0]), "+f"(d[1]), "+f"(d[2]), "+f"(d[3])
        : "r"(a[0]), "r"(a[1]), "r"(a[2]), "r"(a[3]), "r"(b[0]), "r"(b[1]));
}
__device__ __forceinline__ void split_bf16(float v, __nv_bfloat16& h, __nv_bfloat16& l) {
    h = __float2bfloat16(v);
    l = __float2bfloat16(v - __bfloat162float(h));
}

// ---------------------------------------------------------------------------
// Kernel 1: S = softmax(relu(E E^T), axis=1); also emits Shi/Slo (fused)
// ---------------------------------------------------------------------------
__global__ __launch_bounds__(256)
void k_supports(const float* __restrict__ E) {
    const int i   = blockIdx.x;
    const int tid = threadIdx.x;
    __shared__ float ei[FIN];
    __shared__ float row[NN];
    __shared__ float red[8];
    __shared__ float bc0, bc1;

    if (tid < FIN) ei[tid] = E[i*FIN + tid];
    __syncthreads();

    float lmax = 0.0f;
    for (int j = tid; j < NN; j += 256) {
        const float4* ej = reinterpret_cast<const float4*>(E + (size_t)j*FIN);
        float dot = 0.f;
        #pragma unroll
        for (int q = 0; q < 4; q++) {
            float4 v = ej[q];
            dot += v.x*ei[q*4+0] + v.y*ei[q*4+1] + v.z*ei[q*4+2] + v.w*ei[q*4+3];
        }
        float r = fmaxf(dot, 0.f);
        row[j] = r;
        lmax = fmaxf(lmax, r);
    }
    #pragma unroll
    for (int o = 16; o > 0; o >>= 1) lmax = fmaxf(lmax, __shfl_xor_sync(0xffffffffu, lmax, o));
    if ((tid & 31) == 0) red[tid >> 5] = lmax;
    __syncthreads();
    if (tid == 0) {
        float m = red[0];
        #pragma unroll
        for (int w = 1; w < 8; w++) m = fmaxf(m, red[w]);
        bc0 = m;
    }
    __syncthreads();
    const float bmax = bc0;

    float lsum = 0.f;
    for (int j = tid; j < NN; j += 256) {
        float e = expf(row[j] - bmax);
        row[j] = e;
        lsum += e;
    }
    #pragma unroll
    for (int o = 16; o > 0; o >>= 1) lsum += __shfl_xor_sync(0xffffffffu, lsum, o);
    if ((tid & 31) == 0) red[tid >> 5] = lsum;
    __syncthreads();
    if (tid == 0) {
        float s = 0.f;
        #pragma unroll
        for (int w = 0; w < 8; w++) s += red[w];
        bc1 = 1.0f / s;
    }
    __syncthreads();
    const float inv = bc1;
    for (int j = tid; j < NN; j += 256) {
        float v = row[j] * inv;
        size_t o = (size_t)i*NN + j;
        g_S[o] = v;
        __nv_bfloat16 h, l; split_bf16(v, h, l);
        g_Shi[o] = h; g_Slo[o] = l;
    }
}

// ---------------------------------------------------------------------------
// Kernel 2: ST/SThi/STlo (transposed split of S)
// ---------------------------------------------------------------------------
__global__ __launch_bounds__(256)
void k_prepS() {
    __shared__ float t[64][65];
    const int tid = threadIdx.x;
    const int i0 = blockIdx.y*64, j0 = blockIdx.x*64;

    for (int idx = tid; idx < 1024; idx += 256) {
        int r = idx >> 4, q = idx & 15;
        float4 v = *reinterpret_cast<const float4*>(&g_S[(size_t)(i0+r)*NN + j0 + q*4]);
        t[r][q*4+0] = v.x; t[r][q*4+1] = v.y; t[r][q*4+2] = v.z; t[r][q*4+3] = v.w;
    }
    __syncthreads();
    for (int idx = tid; idx < 4096; idx += 256) {
        int c = idx >> 6, r = idx & 63;
        float v = t[r][c];
        __nv_bfloat16 h, l; split_bf16(v, h, l);
        size_t o = (size_t)(j0+c)*NN + i0 + r;
        g_ST[o] = v; g_SThi[o] = h; g_STlo[o] = l;
    }
}

// ---------------------------------------------------------------------------
// Kernel 3: xT[b][ft][n] hi/lo split
// ---------------------------------------------------------------------------
__global__ __launch_bounds__(256)
void k_prepx(const float* __restrict__ x) {
    __shared__ float t[FT][33];
    const int tid = threadIdx.x;
    const int b  = blockIdx.y;
    const int n0 = blockIdx.x*32;
    const float* xb = x + (size_t)b*NN*FT;

    for (int idx = tid; idx < 32*48; idx += 256) {
        int r = idx / 48, q = idx % 48;
        float4 v = *reinterpret_cast<const float4*>(&xb[(size_t)(n0+r)*FT + q*4]);
        t[q*4+0][r] = v.x; t[q*4+1][r] = v.y; t[q*4+2][r] = v.z; t[q*4+3][r] = v.w;
    }
    __syncthreads();
    for (int idx = tid; idx < FT*32; idx += 256) {
        int ft = idx >> 5, n = idx & 31;
        __nv_bfloat16 h, l; split_bf16(t[ft][n], h, l);
        size_t o = ((size_t)b*FT + ft)*NN + n0 + n;
        g_xThi[o] = h; g_xTlo[o] = l;
    }
}

// ---------------------------------------------------------------------------
// Kernel 4: S2T[i][j] = sum_k ST[i,k]*S[j,k]  (3-pass bf16, cp.async double buffer)
// CTA 128x128, 8 warps (2x4), warp tile 64x32, KC=64
// ---------------------------------------------------------------------------
#define S2_BUFH (4*128*S2STR)   // halves per buffer (ATH,ATL,BH,BL)
#define S2_ATH 0
#define S2_ATL (128*S2STR)
#define S2_BH  (2*128*S2STR)
#define S2_BL  (3*128*S2STR)

__global__ __launch_bounds__(256, 1)
void k_s2() {
    extern __shared__ __align__(16) __nv_bfloat16 sh[];
    const int tid = threadIdx.x, w = tid >> 5, lane = tid & 31;
    const int wm = w >> 2, wn = w & 3;
    const int i0 = blockIdx.y*128, j0 = blockIdx.x*128;
    const u32 sb = smem_u32(sh);

    float d[4][4][4];
    #pragma unroll
    for (int mt = 0; mt < 4; mt++)
        #pragma unroll
        for (int nt = 0; nt < 4; nt++)
            #pragma unroll
            for (int e = 0; e < 4; e++) d[mt][nt][e] = 0.f;

    auto stage = [&](int ch) {
        const int n0 = ch*64;
        const u32 bufb = sb + (u32)((ch & 1) * S2_BUFH * 2);
        #pragma unroll
        for (int idx = tid; idx < 4096; idx += 256) {
            int arr = idx >> 10, i = idx & 1023, row = i >> 3, q = i & 7;
            const __nv_bfloat16* src;
            int grow;
            if      (arr == 0) { src = g_SThi; grow = i0 + row; }
            else if (arr == 1) { src = g_STlo; grow = i0 + row; }
            else if (arr == 2) { src = g_Shi;  grow = j0 + row; }
            else               { src = g_Slo;  grow = j0 + row; }
            u32 dst = bufb + (u32)((arr*128*S2STR + row*S2STR + q*8)*2);
            cp16(dst, src + (size_t)grow*NN + n0 + q*8);
        }
    };

    stage(0); CP_COMMIT();

    for (int ch = 0; ch < 32; ch++) {
        if (ch < 31) { stage(ch+1); CP_COMMIT(); CP_WAIT(1); }
        else         { CP_WAIT(0); }
        __syncthreads();

        const u32 bufb = sb + (u32)((ch & 1) * S2_BUFH * 2);
        #pragma unroll
        for (int ks = 0; ks < 4; ks++) {
            u32 ah[4][4], bh[4][2], bl[4][2];
            const int arow = wm*64 + (lane & 15);
            const int acol = ks*16 + (lane >> 4)*8;
            const int brow = wn*32 + (lane & 7);
            const int bcol = ks*16 + ((lane >> 3) & 1)*8;
            #pragma unroll
            for (int nt = 0; nt < 4; nt++) {
                u32 bd = bufb + (u32)(((brow + nt*8)*S2STR + bcol)*2);
                ldsm_x2(bh[nt], bd + S2_BH*2);
                ldsm_x2(bl[nt], bd + S2_BL*2);
            }
            #pragma unroll
            for (int mt = 0; mt < 4; mt++) {
                u32 ad = bufb + (u32)(((arow + mt*16)*S2STR + acol)*2);
                ldsm_x4(ah[mt], ad + S2_ATH*2);
                #pragma unroll
                for (int nt = 0; nt < 4; nt++) {
                    mma_bf16(d[mt][nt], ah[mt], bh[nt]);
                    mma_bf16(d[mt][nt], ah[mt], bl[nt]);
                }
            }
            #pragma unroll
            for (int mt = 0; mt < 4; mt++) {
                u32 ad = bufb + (u32)(((arow + mt*16)*S2STR + acol)*2);
                ldsm_x4(ah[mt], ad + S2_ATL*2);   // reuse regs for lo
                #pragma unroll
                for (int nt = 0; nt < 4; nt++)
                    mma_bf16(d[mt][nt], ah[mt], bh[nt]);
            }
        }
        __syncthreads();
    }
    #pragma unroll
    for (int mt = 0; mt < 4; mt++)
        #pragma unroll
        for (int nt = 0; nt < 4; nt++) {
            int row = i0 + wm*64 + mt*16 + (lane >> 2);
            int col = j0 + wn*32 + nt*8 + (lane & 3)*2;
            *reinterpret_cast<float2*>(&g_S2T[(size_t)row*NN + col]) =
                make_float2(d[mt][nt][0], d[mt][nt][1]);
            *reinterpret_cast<float2*>(&g_S2T[(size_t)(row+8)*NN + col]) =
                make_float2(d[mt][nt][2], d[mt][nt][3]);
        }
}

// ---------------------------------------------------------------------------
// Kernel 5: masked dual-GEMM, cp.async pipeline, A transposed in-SMEM
//   W rows 0-63 : W1[m,n] = ST[m,n]*A[b,n,m]        -> r1
//   W rows 64-127: W2[m,n] = 2*S2T[m,n]*A[b,n,m]    -> r2
// CTA: 256 thr, M=128 (64 m stacked x2), N=96 (ft half), KC=32
// 8 warps (2x4), warp tile 64x24
// ---------------------------------------------------------------------------
// SMEM layout (halves unless noted):
//   W  : parity p at p*10240;  hi +0 (128*40), lo +5120
//   X  : 20480 + p*7680;       hi +0 (96*40),  lo +3840
//   raw (bytes, after 71680B): stST 64*32 f32, stS2 64*32 f32, As 32*68 f32
#define KM_W(p)    ((p)*10240)
#define KM_X(p)    (20480 + (p)*7680)
#define KM_RAWB    71680
#define KM_STB     (KM_RAWB)
#define KM_S2B     (KM_RAWB + 8192)
#define KM_AB      (KM_RAWB + 16384)
#define KM_SMEM    (KM_RAWB + 25088)   // 96768 B

__global__ __launch_bounds__(256, 2)
void k_main(const float* __restrict__ A) {
    extern __shared__ __align__(16) __nv_bfloat16 sh[];
    char* shc = reinterpret_cast<char*>(sh);
    const int tid = threadIdx.x, w = tid >> 5, lane = tid & 31;
    const int wm = w >> 2, wn = w & 3;
    const int m0 = blockIdx.x*64;
    const int nh = blockIdx.y;
    const int b  = blockIdx.z;
    const u32 sb = smem_u32(sh);

    const float* Ab = A + (size_t)b*NN*NN;
    const __nv_bfloat16* xh = g_xThi + ((size_t)b*FT + nh*96)*NN;
    const __nv_bfloat16* xl = g_xTlo + ((size_t)b*FT + nh*96)*NN;
    float* stST = reinterpret_cast<float*>(shc + KM_STB);
    float* stS2 = reinterpret_cast<float*>(shc + KM_S2B);
    float* As   = reinterpret_cast<float*>(shc + KM_AB);

    float d[4][3][4];
    #pragma unroll
    for (int mt = 0; mt < 4; mt++)
        #pragma unroll
        for (int nt = 0; nt < 3; nt++)
            #pragma unroll
            for (int e = 0; e < 4; e++) d[mt][nt][e] = 0.f;

    auto stage = [&](int ch) {
        const int n0 = ch*32;
        const int p = ch & 1;
        #pragma unroll
        for (int idx = tid; idx < 2304; idx += 256) {
            if (idx < 768) {                 // X hi/lo: 2 x 96 rows x 4 chunks
                int sel = idx >= 384;
                int i = idx - sel*384;
                int row = i >> 2, q = i & 3;
                const __nv_bfloat16* src = sel ? xl : xh;
                u32 dst = sb + (u32)((KM_X(p) + sel*3840 + row*WSTR + q*8)*2);
                cp16(dst, src + (size_t)row*NN + n0 + q*8);
            } else if (idx < 1792) {         // raw ST/S2T: 2 x 64 rows x 8 chunks
                int j = idx - 768;
                int sel = j >> 9;
                int i = j & 511;
                int row = i >> 3, q = i & 7;
                const float* src = sel ? g_S2T : g_ST;
                u32 dst = sb + (u32)((sel ? KM_S2B : KM_STB) + (row*32 + q*4)*4);
                cp16(dst, src + (size_t)(m0+row)*NN + n0 + q*4);
            } else {                         // raw A: 32 rows x 16 chunks
                int j = idx - 1792;
                int row = j >> 4, q = j & 15;
                u32 dst = sb + (u32)(KM_AB + (row*68 + q*4)*4);
                cp16(dst, Ab + (size_t)(n0+row)*NN + m0 + q*4);
            }
        }
    };

    auto build = [&](int ch) {
        const int p = ch & 1;
        #pragma unroll
        for (int idx = tid; idx < 1024; idx += 256) {
            int m = idx >> 4, pp = idx & 15, n = 2*pp;
            float2 st = *reinterpret_cast<const float2*>(&stST[m*32 + n]);
            float2 s2 = *reinterpret_cast<const float2*>(&stS2[m*32 + n]);
            float a0 = As[n*68 + m], a1 = As[(n+1)*68 + m];
            float w1x = st.x*a0, w1y = st.y*a1;
            float w2x = 2.f*s2.x*a0, w2y = 2.f*s2.y*a1;
            __nv_bfloat16 h1x,l1x,h1y,l1y,h2x,l2x,h2y,l2y;
            split_bf16(w1x,h1x,l1x); split_bf16(w1y,h1y,l1y);
            split_bf16(w2x,h2x,l2x); split_bf16(w2y,h2y,l2y);
            int base = KM_W(p);
            *reinterpret_cast<__nv_bfloat162*>(shc + (base + m*WSTR + n)*2)          = __nv_bfloat162(h1x, h1y);
            *reinterpret_cast<__nv_bfloat162*>(shc + (base + 5120 + m*WSTR + n)*2)   = __nv_bfloat162(l1x, l1y);
            *reinterpret_cast<__nv_bfloat162*>(shc + (base + (64+m)*WSTR + n)*2)     = __nv_bfloat162(h2x, h2y);
            *reinterpret_cast<__nv_bfloat162*>(shc + (base + 5120 + (64+m)*WSTR + n)*2) = __nv_bfloat162(l2x, l2y);
        }
    };

    auto domma = [&](int ch) {
        const int p = ch & 1;
        const u32 wbase = sb + (u32)(KM_W(p)*2);
        const u32 xbase = sb + (u32)(KM_X(p)*2);
        #pragma unroll
        for (int ks = 0; ks < 2; ks++) {
            u32 ah[4][4], bh[3][2], bl[3][2];
            const int arow = wm*64 + (lane & 15);
            const int acol = ks*16 + (lane >> 4)*8;
            const int brow = wn*24 + (lane & 7);
            const int bcol = ks*16 + ((lane >> 3) & 1)*8;
            #pragma unroll
            for (int nt = 0; nt < 3; nt++) {
                u32 bd = xbase + (u32)(((brow + nt*8)*WSTR + bcol)*2);
                ldsm_x2(bh[nt], bd);
                ldsm_x2(bl[nt], bd + 3840*2);
            }
            #pragma unroll
            for (int mt = 0; mt < 4; mt++) {
                u32 ad = wbase + (u32)(((arow + mt*16)*WSTR + acol)*2);
                ldsm_x4(ah[mt], ad);
                #pragma unroll
                for (int nt = 0; nt < 3; nt++) {
                    mma_bf16(d[mt][nt], ah[mt], bh[nt]);
                    mma_bf16(d[mt][nt], ah[mt], bl[nt]);
                }
            }
            #pragma unroll
            for (int mt = 0; mt < 4; mt++) {
                u32 ad = wbase + (u32)(((arow + mt*16)*WSTR + acol)*2);
                ldsm_x4(ah[mt], ad + 5120*2);   // lo, reuse regs
                #pragma unroll
                for (int nt = 0; nt < 3; nt++)
                    mma_bf16(d[mt][nt], ah[mt], bh[nt]);
            }
        }
    };

    stage(0); CP_COMMIT();
    CP_WAIT(0); __syncthreads();
    build(0); __syncthreads();

    for (int c = 0; c < 64; c++) {
        if (c < 63) { stage(c+1); CP_COMMIT(); }
        domma(c);
        if (c < 63) {
            CP_WAIT(0); __syncthreads();
            build(c+1);
            __syncthreads();
        }
    }

    // epilogue
    #pragma unroll
    for (int mt = 0; mt < 4; mt++)
        #pragma unroll
        for (int nt = 0; nt < 3; nt++) {
            int mrow = wm*64 + mt*16 + (lane >> 2);
            int col  = nh*96 + wn*24 + nt*8 + (lane & 3)*2;
            float* base = (mrow < 64) ? g_r1 : g_r2;
            size_t off = ((size_t)b*NN + m0 + (mrow & 63))*FT + col;
            *reinterpret_cast<float2*>(base + off) = make_float2(d[mt][nt][0], d[mt][nt][1]);
            *reinterpret_cast<float2*>(base + off + 8*FT) = make_float2(d[mt][nt][2], d[mt][nt][3]);
        }
}

// ---------------------------------------------------------------------------
// Kernel 6: theta contraction + diagonal identity term + relu
// ---------------------------------------------------------------------------
__global__ __launch_bounds__(256)
void k_theta(const float* __restrict__ x, const float* __restrict__ A,
             const float* __restrict__ theta, float* __restrict__ out) {
    extern __shared__ float smf[];
    float* r1   = smf;
    float* r2   = smf + 6144;
    float* s0   = smf + 12288;
    float* th1  = smf + 18432;
    float* th2  = smf + 18944;
    float* th02 = smf + 19456;

    const int b   = blockIdx.y;
    const int m0  = blockIdx.x * 32;
    const int tid = threadIdx.x;
    const float* xb = x + (size_t)b*NN*FT;
    const float* Ab = A + (size_t)b*NN*NN;

    for (int i = tid; i < 1536; i += 256) {
        reinterpret_cast<float4*>(r1)[i] =
            reinterpret_cast<const float4*>(g_r1 + ((size_t)b*NN + m0)*FT)[i];
        reinterpret_cast<float4*>(r2)[i] =
            reinterpret_cast<const float4*>(g_r2 + ((size_t)b*NN + m0)*FT)[i];
    }
    for (int i = tid; i < FIN*FOUT; i += 256) {
        th1[i] = theta[512 + i];
        float t2 = theta[1024 + i];
        th2[i]  = t2;
        th02[i] = theta[i] - t2;
    }
    for (int i = tid; i < 32*FT; i += 256) {
        int m = i / FT, ftc = i - m*FT;
        float dg = Ab[(size_t)(m0+m)*NN + m0 + m];
        s0[i] = dg * xb[(size_t)(m0+m)*FT + ftc];
    }
    __syncthreads();

    float* outb = out + (size_t)b*NN*FOUT*TT;
    for (int idx = tid; idx < 32*FOUT*TT; idx += 256) {
        int m = idx / (FOUT*TT);
        int r = idx - m*(FOUT*TT);
        int o = r / TT, t = r - o*TT;
        float val = 0.f;
        #pragma unroll
        for (int f = 0; f < FIN; f++) {
            int ft = f*TT + t;
            val = fmaf(r1[m*FT + ft], th1[f*FOUT + o], val);
            val = fmaf(r2[m*FT + ft], th2[f*FOUT + o], val);
            val = fmaf(s0[m*FT + ft], th02[f*FOUT + o], val);
        }
        outb[(size_t)(m0+m)*FOUT*TT + r] = fmaxf(val, 0.f);
    }
}

// ---------------------------------------------------------------------------
extern "C" void kernel_launch(void* const* d_in, const int* in_sizes, int n_in,
                              void* d_out, int out_size) {
    const float *x = nullptr, *A = nullptr, *E = nullptr, *theta = nullptr;
    for (int i = 0; i < n_in; i++) {
        switch (in_sizes[i]) {
            case BB*NN*FIN*TT:   x     = (const float*)d_in[i]; break;
            case BB*NN*NN:       A     = (const float*)d_in[i]; break;
            case NN*FIN:         E     = (const float*)d_in[i]; break;
            case 3*FIN*FOUT:     theta = (const float*)d_in[i]; break;
        }
    }
    float* out = (float*)d_out;

    k_supports<<<NN, 256>>>(E);
    k_prepS<<<dim3(32, 32), 256>>>();
    k_prepx<<<dim3(64, BB), 256>>>(x);

    const int s2_smem = 2 * S2_BUFH * 2;   // 147456 B
    cudaFuncSetAttribute(k_s2, cudaFuncAttributeMaxDynamicSharedMemorySize, s2_smem);
    k_s2<<<dim3(16, 16), 256, s2_smem>>>();

    cudaFuncSetAttribute(k_main, cudaFuncAttributeMaxDynamicSharedMemorySize, KM_SMEM);
    k_main<<<dim3(32, 2, BB), 256, KM_SMEM>>>(A);

    const int smem_th = 19968 * (int)sizeof(float);
    cudaFuncSetAttribute(k_theta, cudaFuncAttributeMaxDynamicSharedMemorySize, smem_th);
    k_theta<<<dim3(NN/32, BB), 256, smem_th>>>(x, A, theta, out);
}